// round 1
// baseline (speedup 1.0000x reference)
#include <cuda_runtime.h>
#include <cstdint>

#define B_DIM 4096
#define N_CIT 16
#define D_IN  1024
#define D_OUT 1024
#define EPSV  0.01f

// ---------------- scratch (static device allocations; no cudaMalloc) --------
__device__ float g_logits[B_DIM * N_CIT * N_CIT];   // [B, 256]  (pre-softmax, bd added)
__device__ float g_power [B_DIM * N_CIT];           // [B, 16]

// ---------------- f32x2 helpers ---------------------------------------------
__device__ __forceinline__ void ffma2(unsigned long long& d, unsigned long long a,
                                      unsigned long long b) {
    asm("fma.rn.f32x2 %0, %1, %2, %0;" : "+l"(d) : "l"(a), "l"(b));
}
__device__ __forceinline__ unsigned long long pack2(float lo, float hi) {
    unsigned long long r;
    asm("mov.b64 %0, {%1, %2};" : "=l"(r) : "f"(lo), "f"(hi));
    return r;
}
__device__ __forceinline__ float2 unpack2(unsigned long long v) {
    float2 r;
    asm("mov.b64 {%0, %1}, %2;" : "=f"(r.x), "=f"(r.y) : "l"(v));
    return r;
}

// ============================================================================
// Kernel 1: logits[b, c] = sum_i x[b,i] * Wd[n,i,j] + bd[n,j],  c = n*16+j
// 64x64 tile GEMM over [4096, 256], K=1024
// ============================================================================
__global__ __launch_bounds__(256) void logits_kernel(
    const float* __restrict__ x, const float* __restrict__ Wd,
    const float* __restrict__ bd)
{
    __shared__ float Xs[32][68];   // [k][m], padded for alignment
    __shared__ float Ws[32][64];   // [k][c]

    const int bm = blockIdx.y * 64;
    const int bc = blockIdx.x * 64;
    const int tid = threadIdx.x;
    const int tx = tid & 15, ty = tid >> 4;

    float acc[4][4] = {};

    for (int k0 = 0; k0 < D_IN; k0 += 32) {
        // load X tile: 64 rows x 32 k
        #pragma unroll
        for (int j = 0; j < 2; j++) {
            int L = tid + j * 256;          // 0..511
            int m = L >> 3, kq = L & 7;
            float4 v = *(const float4*)&x[(size_t)(bm + m) * D_IN + k0 + kq * 4];
            Xs[kq * 4 + 0][m] = v.x;
            Xs[kq * 4 + 1][m] = v.y;
            Xs[kq * 4 + 2][m] = v.z;
            Xs[kq * 4 + 3][m] = v.w;
        }
        // load Wd tile: 32 k x 64 c, c = n*16 + j  -> Wd[n*16384 + k*16 + j]
        #pragma unroll
        for (int j = 0; j < 2; j++) {
            int L = tid + j * 256;          // 0..511
            int kk = L >> 4, c4 = L & 15;
            int c = bc + c4 * 4;
            int n = c >> 4, jj = c & 15;
            float4 v = *(const float4*)&Wd[(size_t)n * (D_IN * N_CIT) + (size_t)(k0 + kk) * N_CIT + jj];
            *(float4*)&Ws[kk][c4 * 4] = v;
        }
        __syncthreads();
        #pragma unroll
        for (int kk = 0; kk < 32; kk++) {
            float4 a4 = *(const float4*)&Xs[kk][ty * 4];
            float4 b4 = *(const float4*)&Ws[kk][tx * 4];
            float a[4] = {a4.x, a4.y, a4.z, a4.w};
            float b[4] = {b4.x, b4.y, b4.z, b4.w};
            #pragma unroll
            for (int mi = 0; mi < 4; mi++)
                #pragma unroll
                for (int ci = 0; ci < 4; ci++)
                    acc[mi][ci] += a[mi] * b[ci];
        }
        __syncthreads();
    }

    // write logits + bd  (bd is [16,16] contiguous -> bd[c])
    const int cg = bc + tx * 4;
    #pragma unroll
    for (int mi = 0; mi < 4; mi++) {
        int m = bm + ty * 4 + mi;
        float4 r;
        r.x = acc[mi][0] + bd[cg + 0];
        r.y = acc[mi][1] + bd[cg + 1];
        r.z = acc[mi][2] + bd[cg + 2];
        r.w = acc[mi][3] + bd[cg + 3];
        *(float4*)&g_logits[(size_t)m * 256 + cg] = r;
    }
}

// ============================================================================
// Kernel 2: per-batch softmax + 16x16 linear solve -> power[b, 16]
//   M16[r][i] = (i==r) ? 1 : -(1-eps)*dall[i*16+r];  solve M16 z = 1
//   z16 = 1 + eps * sum(z)
//   power[j] = z[j]*(1-eps)*dall[j*16+j] + z16/16 - 1/16
// ============================================================================
__global__ __launch_bounds__(256) void power_kernel()
{
    int b = blockIdx.x * blockDim.x + threadIdx.x;
    if (b >= B_DIM) return;
    const float* lg = g_logits + (size_t)b * 256;

    float dl[256];
    for (int n = 0; n < N_CIT; n++) {
        float mx = lg[n * 16];
        for (int j = 1; j < 16; j++) mx = fmaxf(mx, lg[n * 16 + j]);
        float s = 0.f;
        for (int j = 0; j < 16; j++) {
            float e = expf(lg[n * 16 + j] - mx);
            dl[n * 16 + j] = e;
            s += e;
        }
        float inv = 1.f / s;
        for (int j = 0; j < 16; j++) dl[n * 16 + j] *= inv;
    }

    const float ome = 1.f - EPSV;
    float A[16][17];
    for (int r = 0; r < 16; r++) {
        for (int i = 0; i < 16; i++)
            A[r][i] = (i == r) ? 1.f : -ome * dl[i * 16 + r];
        A[r][16] = 1.f;
    }
    // Gaussian elimination (column-diagonally-dominant -> no pivoting needed)
    for (int p = 0; p < 16; p++) {
        float inv = 1.f / A[p][p];
        for (int c = p; c < 17; c++) A[p][c] *= inv;
        for (int r = p + 1; r < 16; r++) {
            float f = A[r][p];
            for (int c = p; c < 17; c++) A[r][c] -= f * A[p][c];
        }
    }
    float z[16];
    for (int r = 15; r >= 0; r--) {
        float s = A[r][16];
        for (int c = r + 1; c < 16; c++) s -= A[r][c] * z[c];
        z[r] = s;
    }
    float zs = 0.f;
    for (int i = 0; i < 16; i++) zs += z[i];
    float z16 = 1.f + EPSV * zs;
    float add = z16 * (1.f / 16.f) - (1.f / 16.f);
    for (int j = 0; j < 16; j++)
        g_power[(size_t)b * 16 + j] = z[j] * ome * dl[j * 16 + j] + add;
}

// ============================================================================
// Kernel 3: y[b,o] = sum_{k=0..16383} (power[b, k>>10] * x[b, k&1023]) * WyF[k, o]
//                  + sum_n power[b,n] * by[n, o]
// 128x128x16 tiles, 256 threads, 8x8 microtiles with packed f32x2 FMA.
// ============================================================================
__global__ __launch_bounds__(256, 1) void main_gemm(
    const float* __restrict__ x, const float* __restrict__ Wy,
    const float* __restrict__ by, float* __restrict__ out)
{
    __shared__ float As[16][128];   // [k][m], A = power-scaled x
    __shared__ float Bs[16][128];   // [k][o]
    __shared__ float Ps[128][17];   // power rows for this block (padded)

    const int bm = blockIdx.y * 128;
    const int bn = blockIdx.x * 128;
    const int tid = threadIdx.x;
    const int tx = tid & 15, ty = tid >> 4;

    // preload power rows
    #pragma unroll
    for (int j = 0; j < 8; j++) {
        int L = tid + j * 256;            // 0..2047
        int m = L >> 4, q = L & 15;
        Ps[m][q] = g_power[(size_t)(bm + m) * 16 + q];
    }
    __syncthreads();

    unsigned long long acc[8][4];
    #pragma unroll
    for (int mi = 0; mi < 8; mi++)
        #pragma unroll
        for (int cj = 0; cj < 4; cj++) acc[mi][cj] = 0ull;   // two packed +0.0f

    for (int k0 = 0; k0 < N_CIT * D_IN; k0 += 16) {
        const int n = k0 >> 10;
        const int ki = k0 & 1023;
        // A tile: generate power[b,n]*x[b,i]
        #pragma unroll
        for (int j = 0; j < 2; j++) {
            int L = tid + j * 256;        // 0..511
            int m = L & 127, kq = L >> 7; // kq 0..3
            float4 v = *(const float4*)&x[(size_t)(bm + m) * D_IN + ki + kq * 4];
            float p = Ps[m][n];
            As[kq * 4 + 0][m] = v.x * p;
            As[kq * 4 + 1][m] = v.y * p;
            As[kq * 4 + 2][m] = v.z * p;
            As[kq * 4 + 3][m] = v.w * p;
        }
        // B tile: Wy flattened [16384, 1024]
        #pragma unroll
        for (int j = 0; j < 2; j++) {
            int L = tid + j * 256;        // 0..511
            int kk = L >> 5, c4 = L & 31;
            *(float4*)&Bs[kk][c4 * 4] =
                *(const float4*)&Wy[(size_t)(k0 + kk) * D_OUT + bn + c4 * 4];
        }
        __syncthreads();
        #pragma unroll
        for (int kk = 0; kk < 16; kk++) {
            float4 a0 = *(const float4*)&As[kk][ty * 8];
            float4 a1 = *(const float4*)&As[kk][ty * 8 + 4];
            float4 b0 = *(const float4*)&Bs[kk][tx * 8];
            float4 b1 = *(const float4*)&Bs[kk][tx * 8 + 4];
            unsigned long long bp[4];
            bp[0] = pack2(b0.x, b0.y);
            bp[1] = pack2(b0.z, b0.w);
            bp[2] = pack2(b1.x, b1.y);
            bp[3] = pack2(b1.z, b1.w);
            float av[8] = {a0.x, a0.y, a0.z, a0.w, a1.x, a1.y, a1.z, a1.w};
            #pragma unroll
            for (int mi = 0; mi < 8; mi++) {
                unsigned long long ap = pack2(av[mi], av[mi]);
                #pragma unroll
                for (int cj = 0; cj < 4; cj++)
                    ffma2(acc[mi][cj], ap, bp[cj]);
            }
        }
        __syncthreads();
    }

    // unpack accumulators
    float accf[8][8];
    #pragma unroll
    for (int mi = 0; mi < 8; mi++)
        #pragma unroll
        for (int cj = 0; cj < 4; cj++) {
            float2 v = unpack2(acc[mi][cj]);
            accf[mi][cj * 2 + 0] = v.x;
            accf[mi][cj * 2 + 1] = v.y;
        }

    // bias term: + sum_n Ps[m][n] * by[n, c]
    #pragma unroll
    for (int n = 0; n < N_CIT; n++) {
        float4 u0 = *(const float4*)&by[(size_t)n * D_OUT + bn + tx * 8];
        float4 u1 = *(const float4*)&by[(size_t)n * D_OUT + bn + tx * 8 + 4];
        float bc[8] = {u0.x, u0.y, u0.z, u0.w, u1.x, u1.y, u1.z, u1.w};
        #pragma unroll
        for (int mi = 0; mi < 8; mi++) {
            float p = Ps[ty * 8 + mi][n];
            #pragma unroll
            for (int c = 0; c < 8; c++) accf[mi][c] += p * bc[c];
        }
    }

    // write out
    #pragma unroll
    for (int mi = 0; mi < 8; mi++) {
        int m = bm + ty * 8 + mi;
        float4 o0 = make_float4(accf[mi][0], accf[mi][1], accf[mi][2], accf[mi][3]);
        float4 o1 = make_float4(accf[mi][4], accf[mi][5], accf[mi][6], accf[mi][7]);
        *(float4*)&out[(size_t)m * D_OUT + bn + tx * 8] = o0;
        *(float4*)&out[(size_t)m * D_OUT + bn + tx * 8 + 4] = o1;
    }
}

// ============================================================================
extern "C" void kernel_launch(void* const* d_in, const int* in_sizes, int n_in,
                              void* d_out, int out_size)
{
    const float* x  = (const float*)d_in[0];
    const float* Wy = (const float*)d_in[1];
    const float* by = (const float*)d_in[2];
    const float* Wd = (const float*)d_in[3];
    const float* bd = (const float*)d_in[4];
    float* out = (float*)d_out;

    logits_kernel<<<dim3(256 / 64, B_DIM / 64), 256>>>(x, Wd, bd);
    power_kernel<<<B_DIM / 256, 256>>>();
    main_gemm<<<dim3(D_OUT / 128, B_DIM / 128), 256>>>(x, Wy, by, out);
}